// round 7
// baseline (speedup 1.0000x reference)
#include <cuda_runtime.h>

#define NN 50000
#define EE 1600000
#define DD 128
#define GG 64
#define LL 3

// ---------------- scratch (static device globals; no allocation) ----------------
__device__ float g_bufA[NN * DD];   // ping-pong node features
__device__ float g_bufB[NN * DD];
__device__ float g_Sd[NN * DD];     // per-node sum of X[src] over data edges
__device__ float g_Sc[NN * DD];     // per-node sum over ctrl edges
__device__ int   g_cntd[NN];        // zero at entry (zeroed by k_pool tail)
__device__ int   g_cntc[NN];
__device__ int   g_rowptr[NN + 1];
__device__ int   g_cursor[NN];
__device__ unsigned int g_edge[EE]; // src | (type<<31), sorted by dst

// ---------------- f32x2 packed helpers ----------------
__device__ __forceinline__ unsigned long long ffma2(unsigned long long a,
                                                    unsigned long long b,
                                                    unsigned long long c) {
    unsigned long long d;
    asm("fma.rn.f32x2 %0, %1, %2, %3;" : "=l"(d) : "l"(a), "l"(b), "l"(c));
    return d;
}
__device__ __forceinline__ unsigned long long pk2(float v) {
    unsigned long long d;
    unsigned int u = __float_as_uint(v);
    asm("mov.b64 %0, {%1, %2};" : "=l"(d) : "r"(u), "r"(u));
    return d;
}

// ---------------- CSR build ----------------
// g_cntd/g_cntc are zero on entry: statics start zeroed; k_pool re-zeros them.
__global__ void k_count(const int* __restrict__ dst, const int* __restrict__ et) {
    int e = blockIdx.x * blockDim.x + threadIdx.x;
    if (e < EE) {
        int d = dst[e];
        if (et[e] == 0) atomicAdd(&g_cntd[d], 1);
        else            atomicAdd(&g_cntc[d], 1);
    }
}

__global__ void __launch_bounds__(1024) k_scan() {
    __shared__ int warp_sums[32];
    __shared__ int s_carry;
    int tid = threadIdx.x;
    int lane = tid & 31, wid = tid >> 5;
    if (tid == 0) s_carry = 0;
    __syncthreads();
    for (int base = 0; base < NN; base += 1024) {
        int i = base + tid;
        int v = (i < NN) ? (g_cntd[i] + g_cntc[i]) : 0;
        int x = v;
        #pragma unroll
        for (int off = 1; off < 32; off <<= 1) {
            int y = __shfl_up_sync(0xffffffffu, x, off);
            if (lane >= off) x += y;
        }
        if (lane == 31) warp_sums[wid] = x;
        __syncthreads();
        if (tid < 32) {
            int w = warp_sums[tid];
            #pragma unroll
            for (int off = 1; off < 32; off <<= 1) {
                int y = __shfl_up_sync(0xffffffffu, w, off);
                if (tid >= off) w += y;
            }
            warp_sums[tid] = w;
        }
        __syncthreads();
        int woff = (wid > 0) ? warp_sums[wid - 1] : 0;
        int incl = x + woff;
        if (i < NN) {
            int rp = s_carry + incl - v;
            g_rowptr[i] = rp;
            g_cursor[i] = rp;
        }
        int total = warp_sums[31];
        __syncthreads();
        if (tid == 0) s_carry += total;
        __syncthreads();
    }
    if (tid == 0) g_rowptr[NN] = s_carry;
}

__global__ void k_fill(const int* __restrict__ src, const int* __restrict__ dst,
                       const int* __restrict__ et) {
    int e = blockIdx.x * blockDim.x + threadIdx.x;
    if (e < EE) {
        int d = dst[e];
        int pos = atomicAdd(&g_cursor[d], 1);
        g_edge[pos] = (unsigned int)src[e] | ((unsigned int)et[e] << 31);
    }
}

// ---------------- edge aggregation: warp per dst node ----------------
__global__ void __launch_bounds__(256) k_aggregate(const float* __restrict__ X) {
    int w = (blockIdx.x * blockDim.x + threadIdx.x) >> 5;
    int lane = threadIdx.x & 31;
    if (w >= NN) return;
    int beg = g_rowptr[w], end = g_rowptr[w + 1];
    const float4* X4 = (const float4*)X;
    float4 ad = make_float4(0.f, 0.f, 0.f, 0.f);
    float4 ac = make_float4(0.f, 0.f, 0.f, 0.f);
    int j = beg;
    for (; j + 1 < end; j += 2) {
        unsigned int e0 = g_edge[j];
        unsigned int e1 = g_edge[j + 1];
        float4 v0 = __ldg(X4 + (int)(e0 & 0x7fffffffu) * 32 + lane);
        float4 v1 = __ldg(X4 + (int)(e1 & 0x7fffffffu) * 32 + lane);
        if (e0 >> 31) { ac.x += v0.x; ac.y += v0.y; ac.z += v0.z; ac.w += v0.w; }
        else          { ad.x += v0.x; ad.y += v0.y; ad.z += v0.z; ad.w += v0.w; }
        if (e1 >> 31) { ac.x += v1.x; ac.y += v1.y; ac.z += v1.z; ac.w += v1.w; }
        else          { ad.x += v1.x; ad.y += v1.y; ad.z += v1.z; ad.w += v1.w; }
    }
    if (j < end) {
        unsigned int e0 = g_edge[j];
        float4 v0 = __ldg(X4 + (int)(e0 & 0x7fffffffu) * 32 + lane);
        if (e0 >> 31) { ac.x += v0.x; ac.y += v0.y; ac.z += v0.z; ac.w += v0.w; }
        else          { ad.x += v0.x; ad.y += v0.y; ad.z += v0.z; ad.w += v0.w; }
    }
    ((float4*)g_Sd)[w * 32 + lane] = ad;
    ((float4*)g_Sc)[w * 32 + lane] = ac;
}

// ---------------- triple GEMM + bias + relu (8 rows per warp) ----------------
// X' = relu(Sd@Wd + Sc@Wc + X@Ws + cntd*bd + cntc*bc + bs)
// Block: 256 threads (8 warps), 64 rows x 128 cols. Warp ty: rows ty*8..+7.
// Lane tx: cols tx*4..+3. Each W LDG.128 feeds 16 FFMA2 (vs 8 in round-1),
// halving duplicated W L2 traffic. Dynamic smem: sX[3][128][64] = 96KB.
#define GROWS 64
__global__ void __launch_bounds__(256, 1) k_gemm(
    const float* __restrict__ Xin,
    const float* __restrict__ Wd, const float* __restrict__ bd,
    const float* __restrict__ Wc, const float* __restrict__ bc,
    const float* __restrict__ Ws, const float* __restrict__ bs,
    float* __restrict__ Y)
{
    extern __shared__ __align__(16) float sX[]; // [3][DD][GROWS]
    int tid = threadIdx.x;
    int rowbase = blockIdx.x * GROWS;

    // ---- tile load (transposed, k-major) ----
    {
        int r = tid & 63;
        int kq = tid >> 6; // 0..3, covers 32 k each (8 float4)
        int row = rowbase + r;
        const float* srcs[3] = { g_Sd, g_Sc, Xin };
        #pragma unroll
        for (int m = 0; m < 3; m++) {
            float* sXm = sX + m * DD * GROWS;
            const float4* s4 = (const float4*)(srcs[m] + row * DD);
            #pragma unroll
            for (int q = 0; q < 8; q++) {
                float4 a;
                if (row < NN) a = __ldg(s4 + kq * 8 + q);
                else          a = make_float4(0.f, 0.f, 0.f, 0.f);
                int k0 = kq * 32 + q * 4;
                sXm[(k0 + 0) * GROWS + r] = a.x;
                sXm[(k0 + 1) * GROWS + r] = a.y;
                sXm[(k0 + 2) * GROWS + r] = a.z;
                sXm[(k0 + 3) * GROWS + r] = a.w;
            }
        }
    }
    __syncthreads();

    int tx = tid & 31;
    int ty = tid >> 5;
    const float4* W4[3] = { (const float4*)Wd, (const float4*)Wc, (const float4*)Ws };
    // acc[rp][c]: row-pair ty*8 + 2*rp (+1), col tx*4 + c
    unsigned long long acc[4][4];
    #pragma unroll
    for (int rp = 0; rp < 4; rp++)
        #pragma unroll
        for (int c = 0; c < 4; c++) acc[rp][c] = 0ull;

    #pragma unroll 2
    for (int k = 0; k < DD; k++) {
        #pragma unroll
        for (int m = 0; m < 3; m++) {
            float4 wv = __ldg(W4[m] + k * 32 + tx);
            unsigned long long w0 = pk2(wv.x), w1 = pk2(wv.y);
            unsigned long long w2 = pk2(wv.z), w3 = pk2(wv.w);
            const unsigned long long* xp =
                (const unsigned long long*)(sX + (m * DD + k) * GROWS);
            unsigned long long xa = xp[ty * 4 + 0]; // rows ty*8+0,1
            unsigned long long xb = xp[ty * 4 + 1]; // rows ty*8+2,3
            unsigned long long xc = xp[ty * 4 + 2]; // rows ty*8+4,5
            unsigned long long xd = xp[ty * 4 + 3]; // rows ty*8+6,7
            acc[0][0] = ffma2(xa, w0, acc[0][0]);
            acc[0][1] = ffma2(xa, w1, acc[0][1]);
            acc[0][2] = ffma2(xa, w2, acc[0][2]);
            acc[0][3] = ffma2(xa, w3, acc[0][3]);
            acc[1][0] = ffma2(xb, w0, acc[1][0]);
            acc[1][1] = ffma2(xb, w1, acc[1][1]);
            acc[1][2] = ffma2(xb, w2, acc[1][2]);
            acc[1][3] = ffma2(xb, w3, acc[1][3]);
            acc[2][0] = ffma2(xc, w0, acc[2][0]);
            acc[2][1] = ffma2(xc, w1, acc[2][1]);
            acc[2][2] = ffma2(xc, w2, acc[2][2]);
            acc[2][3] = ffma2(xc, w3, acc[2][3]);
            acc[3][0] = ffma2(xd, w0, acc[3][0]);
            acc[3][1] = ffma2(xd, w1, acc[3][1]);
            acc[3][2] = ffma2(xd, w2, acc[3][2]);
            acc[3][3] = ffma2(xd, w3, acc[3][3]);
        }
    }

    float4 bdv = __ldg((const float4*)bd + tx);
    float4 bcv = __ldg((const float4*)bc + tx);
    float4 bsv = __ldg((const float4*)bs + tx);
    #pragma unroll
    for (int r = 0; r < 8; r++) {
        int row = rowbase + ty * 8 + r;
        if (row >= NN) continue;
        int rp = r >> 1, h = r & 1;
        float2 c0 = *(float2*)&acc[rp][0];
        float2 c1 = *(float2*)&acc[rp][1];
        float2 c2 = *(float2*)&acc[rp][2];
        float2 c3 = *(float2*)&acc[rp][3];
        float4 o;
        o.x = h ? c0.y : c0.x;
        o.y = h ? c1.y : c1.x;
        o.z = h ? c2.y : c2.x;
        o.w = h ? c3.y : c3.x;
        float cd = (float)g_cntd[row];
        float cc = (float)g_cntc[row];
        o.x = fmaxf(fmaf(cd, bdv.x, fmaf(cc, bcv.x, o.x + bsv.x)), 0.f);
        o.y = fmaxf(fmaf(cd, bdv.y, fmaf(cc, bcv.y, o.y + bsv.y)), 0.f);
        o.z = fmaxf(fmaf(cd, bdv.z, fmaf(cc, bcv.z, o.z + bsv.z)), 0.f);
        o.w = fmaxf(fmaf(cd, bdv.w, fmaf(cc, bcv.w, o.w + bsv.w)), 0.f);
        ((float4*)Y)[row * 32 + tx] = o;
    }
}

// ---------------- mean pool per graph + count re-zero (last launch) ----------
__global__ void __launch_bounds__(DD) k_pool(const float* __restrict__ X,
                                             const int* __restrict__ batch,
                                             float* __restrict__ out) {
    int g = blockIdx.x;
    int c = threadIdx.x;
    int lo = 0, hi = NN;
    while (lo < hi) { int m = (lo + hi) >> 1; if (batch[m] < g) lo = m + 1; else hi = m; }
    int start = lo;
    lo = start; hi = NN;
    while (lo < hi) { int m = (lo + hi) >> 1; if (batch[m] < g + 1) lo = m + 1; else hi = m; }
    int end = lo;

    float s0 = 0.f, s1 = 0.f, s2 = 0.f, s3 = 0.f;
    int n = start;
    for (; n + 3 < end; n += 4) {
        s0 += X[(n + 0) * DD + c];
        s1 += X[(n + 1) * DD + c];
        s2 += X[(n + 2) * DD + c];
        s3 += X[(n + 3) * DD + c];
    }
    for (; n < end; n++) s0 += X[n * DD + c];
    float s = (s0 + s1) + (s2 + s3);
    float cnt = (float)(end - start);
    out[g * DD + c] = s / fmaxf(cnt, 1.0f);

    for (int i = g * DD + c; i < NN; i += GG * DD) {
        g_cntd[i] = 0;
        g_cntc[i] = 0;
    }
}

// ---------------- launch ----------------
extern "C" void kernel_launch(void* const* d_in, const int* in_sizes, int n_in,
                              void* d_out, int out_size) {
    const float* X  = (const float*)d_in[0];
    const float* Wd = (const float*)d_in[1];
    const float* bd = (const float*)d_in[2];
    const float* Wc = (const float*)d_in[3];
    const float* bc = (const float*)d_in[4];
    const float* Ws = (const float*)d_in[5];
    const float* bs = (const float*)d_in[6];
    const int* ei   = (const int*)d_in[7];
    const int* et   = (const int*)d_in[8];
    const int* bid  = (const int*)d_in[9];
    const int* srcp = ei;
    const int* dstp = ei + EE;

    void* pA = nullptr;
    void* pB = nullptr;
    cudaGetSymbolAddress(&pA, g_bufA);
    cudaGetSymbolAddress(&pB, g_bufB);
    float* A = (float*)pA;
    float* B = (float*)pB;

    const int GEMM_SMEM = 3 * DD * GROWS * sizeof(float); // 96KB
    cudaFuncSetAttribute(k_gemm, cudaFuncAttributeMaxDynamicSharedMemorySize,
                         GEMM_SMEM);

    // CSR build (counts arrive zeroed; k_pool re-zeros them at the end)
    k_count<<<(EE + 255) / 256, 256>>>(dstp, et);
    k_scan<<<1, 1024>>>();
    k_fill<<<(EE + 255) / 256, 256>>>(srcp, dstp, et);

    const float* cur = X;
    float* outs[3] = { A, B, A };
    for (int l = 0; l < LL; l++) {
        k_aggregate<<<(NN * 32 + 255) / 256, 256>>>(cur); // ncu window (l=0)
        k_gemm<<<(NN + GROWS - 1) / GROWS, 256, GEMM_SMEM>>>(cur,
                                        Wd + l * DD * DD, bd + l * DD,
                                        Wc + l * DD * DD, bc + l * DD,
                                        Ws + l * DD * DD, bs + l * DD,
                                        outs[l]);
        cur = outs[l];
    }
    k_pool<<<GG, DD>>>(cur, bid, (float*)d_out);
}

// round 10
// speedup vs baseline: 1.2242x; 1.2242x over previous
#include <cuda_runtime.h>

#define NN 50000
#define EE 1600000
#define DD 128
#define GG 64
#define LL 3

// ---------------- scratch (static device globals; no allocation) ----------------
__device__ float g_bufA[NN * DD];   // ping-pong node features
__device__ float g_bufB[NN * DD];
__device__ float g_Sd[NN * DD];     // per-node sum of X[src] over data edges
__device__ float g_Sc[NN * DD];     // per-node sum over ctrl edges
__device__ int   g_deg[NN];         // total degree; zero at entry (k_pool re-zeros)
__device__ int   g_cntd[NN];        // written by k_aggregate each call
__device__ int   g_cntc[NN];
__device__ int   g_rowptr[NN + 1];
__device__ int   g_cursor[NN];
__device__ unsigned int g_edge[EE]; // src | (type<<31), sorted by dst

// ---------------- f32x2 packed helpers ----------------
__device__ __forceinline__ unsigned long long ffma2(unsigned long long a,
                                                    unsigned long long b,
                                                    unsigned long long c) {
    unsigned long long d;
    asm("fma.rn.f32x2 %0, %1, %2, %3;" : "=l"(d) : "l"(a), "l"(b), "l"(c));
    return d;
}
__device__ __forceinline__ unsigned long long pk2(float v) {
    unsigned long long d;
    unsigned int u = __float_as_uint(v);
    asm("mov.b64 %0, {%1, %2};" : "=l"(d) : "r"(u), "r"(u));
    return d;
}

// ---------------- CSR build ----------------
// g_deg is zero on entry: statics start zeroed; k_pool re-zeros it.
__global__ void k_count(const int* __restrict__ dst) {
    int e = blockIdx.x * blockDim.x + threadIdx.x;
    if (e < EE) atomicAdd(&g_deg[dst[e]], 1);
}

__global__ void __launch_bounds__(1024) k_scan() {
    __shared__ int warp_sums[32];
    __shared__ int s_carry;
    int tid = threadIdx.x;
    int lane = tid & 31, wid = tid >> 5;
    if (tid == 0) s_carry = 0;
    __syncthreads();
    for (int base = 0; base < NN; base += 1024) {
        int i = base + tid;
        int v = (i < NN) ? g_deg[i] : 0;
        int x = v;
        #pragma unroll
        for (int off = 1; off < 32; off <<= 1) {
            int y = __shfl_up_sync(0xffffffffu, x, off);
            if (lane >= off) x += y;
        }
        if (lane == 31) warp_sums[wid] = x;
        __syncthreads();
        if (tid < 32) {
            int w = warp_sums[tid];
            #pragma unroll
            for (int off = 1; off < 32; off <<= 1) {
                int y = __shfl_up_sync(0xffffffffu, w, off);
                if (tid >= off) w += y;
            }
            warp_sums[tid] = w;
        }
        __syncthreads();
        int woff = (wid > 0) ? warp_sums[wid - 1] : 0;
        int incl = x + woff;
        if (i < NN) {
            int rp = s_carry + incl - v;
            g_rowptr[i] = rp;
            g_cursor[i] = rp;
        }
        int total = warp_sums[31];
        __syncthreads();
        if (tid == 0) s_carry += total;
        __syncthreads();
    }
    if (tid == 0) g_rowptr[NN] = s_carry;
}

__global__ void k_fill(const int* __restrict__ src, const int* __restrict__ dst,
                       const int* __restrict__ et) {
    int e = blockIdx.x * blockDim.x + threadIdx.x;
    if (e < EE) {
        int d = dst[e];
        int pos = atomicAdd(&g_cursor[d], 1);
        g_edge[pos] = (unsigned int)src[e] | ((unsigned int)et[e] << 31);
    }
}

// ---------------- edge aggregation: warp per dst node (+ type counts) --------
__global__ void __launch_bounds__(256) k_aggregate(const float* __restrict__ X) {
    int w = (blockIdx.x * blockDim.x + threadIdx.x) >> 5;
    int lane = threadIdx.x & 31;
    if (w >= NN) return;
    int beg = g_rowptr[w], end = g_rowptr[w + 1];
    const float4* X4 = (const float4*)X;
    float4 ad = make_float4(0.f, 0.f, 0.f, 0.f);
    float4 ac = make_float4(0.f, 0.f, 0.f, 0.f);
    int nc = 0;  // ctrl-edge count (uniform across lanes)
    int j = beg;
    for (; j + 1 < end; j += 2) {
        unsigned int e0 = g_edge[j];
        unsigned int e1 = g_edge[j + 1];
        float4 v0 = __ldg(X4 + (int)(e0 & 0x7fffffffu) * 32 + lane);
        float4 v1 = __ldg(X4 + (int)(e1 & 0x7fffffffu) * 32 + lane);
        nc += (int)(e0 >> 31) + (int)(e1 >> 31);
        if (e0 >> 31) { ac.x += v0.x; ac.y += v0.y; ac.z += v0.z; ac.w += v0.w; }
        else          { ad.x += v0.x; ad.y += v0.y; ad.z += v0.z; ad.w += v0.w; }
        if (e1 >> 31) { ac.x += v1.x; ac.y += v1.y; ac.z += v1.z; ac.w += v1.w; }
        else          { ad.x += v1.x; ad.y += v1.y; ad.z += v1.z; ad.w += v1.w; }
    }
    if (j < end) {
        unsigned int e0 = g_edge[j];
        float4 v0 = __ldg(X4 + (int)(e0 & 0x7fffffffu) * 32 + lane);
        nc += (int)(e0 >> 31);
        if (e0 >> 31) { ac.x += v0.x; ac.y += v0.y; ac.z += v0.z; ac.w += v0.w; }
        else          { ad.x += v0.x; ad.y += v0.y; ad.z += v0.z; ad.w += v0.w; }
    }
    ((float4*)g_Sd)[w * 32 + lane] = ad;
    ((float4*)g_Sc)[w * 32 + lane] = ac;
    if (lane == 0) {
        g_cntc[w] = nc;
        g_cntd[w] = (end - beg) - nc;
    }
}

// ---------------- triple GEMM + bias + relu (64 rows, k-chunked smem) --------
// X' = relu(Sd@Wd + Sc@Wc + X@Ws + cntd*bd + cntc*bc + bs)
// Block: 256 threads (8 warps), 64 rows x 128 cols; warp ty: rows ty*8..+7,
// lane tx: cols tx*4..+3. X staged in k-chunks of 32 -> smem 24KB, so
// occupancy stays multi-block while each W LDG.128 feeds 16 FFMA2.
#define GROWS 64
#define KC 32
__global__ void __launch_bounds__(256) k_gemm(
    const float* __restrict__ Xin,
    const float* __restrict__ Wd, const float* __restrict__ bd,
    const float* __restrict__ Wc, const float* __restrict__ bc,
    const float* __restrict__ Ws, const float* __restrict__ bs,
    float* __restrict__ Y)
{
    __shared__ __align__(16) float sX[3][KC][GROWS]; // 24KB
    int tid = threadIdx.x;
    int tx = tid & 31;
    int ty = tid >> 5;
    int rowbase = blockIdx.x * GROWS;

    const float* srcs[3] = { g_Sd, g_Sc, Xin };
    const float4* W4[3] = { (const float4*)Wd, (const float4*)Wc, (const float4*)Ws };

    // acc[rp][c]: row pair (ty*8+2rp, +1), col tx*4+c
    unsigned long long acc[4][4];
    #pragma unroll
    for (int rp = 0; rp < 4; rp++)
        #pragma unroll
        for (int c = 0; c < 4; c++) acc[rp][c] = 0ull;

    int lr = tid & 63;          // row within tile for loading
    int kq = tid >> 6;          // 0..3 -> 8 k each
    int lrow = rowbase + lr;

    #pragma unroll 1
    for (int kt = 0; kt < DD / KC; kt++) {
        __syncthreads();
        // ---- stage k-chunk of all 3 matrices (transposed) ----
        #pragma unroll
        for (int m = 0; m < 3; m++) {
            const float4* s4 = (const float4*)(srcs[m] + lrow * DD) + kt * (KC / 4);
            #pragma unroll
            for (int q = 0; q < 2; q++) {
                float4 a = (lrow < NN) ? __ldg(s4 + kq * 2 + q)
                                       : make_float4(0.f, 0.f, 0.f, 0.f);
                int k0 = kq * 8 + q * 4;
                sX[m][k0 + 0][lr] = a.x;
                sX[m][k0 + 1][lr] = a.y;
                sX[m][k0 + 2][lr] = a.z;
                sX[m][k0 + 3][lr] = a.w;
            }
        }
        __syncthreads();
        // ---- compute over this k-chunk ----
        #pragma unroll 2
        for (int k = 0; k < KC; k++) {
            int gk = kt * KC + k;
            #pragma unroll
            for (int m = 0; m < 3; m++) {
                float4 wv = __ldg(W4[m] + gk * 32 + tx);
                unsigned long long w0 = pk2(wv.x), w1 = pk2(wv.y);
                unsigned long long w2 = pk2(wv.z), w3 = pk2(wv.w);
                const unsigned long long* xp =
                    (const unsigned long long*)&sX[m][k][ty * 8];
                unsigned long long xa = xp[0];
                unsigned long long xb = xp[1];
                unsigned long long xc = xp[2];
                unsigned long long xd = xp[3];
                acc[0][0] = ffma2(xa, w0, acc[0][0]);
                acc[0][1] = ffma2(xa, w1, acc[0][1]);
                acc[0][2] = ffma2(xa, w2, acc[0][2]);
                acc[0][3] = ffma2(xa, w3, acc[0][3]);
                acc[1][0] = ffma2(xb, w0, acc[1][0]);
                acc[1][1] = ffma2(xb, w1, acc[1][1]);
                acc[1][2] = ffma2(xb, w2, acc[1][2]);
                acc[1][3] = ffma2(xb, w3, acc[1][3]);
                acc[2][0] = ffma2(xc, w0, acc[2][0]);
                acc[2][1] = ffma2(xc, w1, acc[2][1]);
                acc[2][2] = ffma2(xc, w2, acc[2][2]);
                acc[2][3] = ffma2(xc, w3, acc[2][3]);
                acc[3][0] = ffma2(xd, w0, acc[3][0]);
                acc[3][1] = ffma2(xd, w1, acc[3][1]);
                acc[3][2] = ffma2(xd, w2, acc[3][2]);
                acc[3][3] = ffma2(xd, w3, acc[3][3]);
            }
        }
    }

    float4 bdv = __ldg((const float4*)bd + tx);
    float4 bcv = __ldg((const float4*)bc + tx);
    float4 bsv = __ldg((const float4*)bs + tx);
    #pragma unroll
    for (int r = 0; r < 8; r++) {
        int row = rowbase + ty * 8 + r;
        if (row >= NN) continue;
        int rp = r >> 1, h = r & 1;
        float2 c0 = *(float2*)&acc[rp][0];
        float2 c1 = *(float2*)&acc[rp][1];
        float2 c2 = *(float2*)&acc[rp][2];
        float2 c3 = *(float2*)&acc[rp][3];
        float4 o;
        o.x = h ? c0.y : c0.x;
        o.y = h ? c1.y : c1.x;
        o.z = h ? c2.y : c2.x;
        o.w = h ? c3.y : c3.x;
        float cd = (float)g_cntd[row];
        float cc = (float)g_cntc[row];
        o.x = fmaxf(fmaf(cd, bdv.x, fmaf(cc, bcv.x, o.x + bsv.x)), 0.f);
        o.y = fmaxf(fmaf(cd, bdv.y, fmaf(cc, bcv.y, o.y + bsv.y)), 0.f);
        o.z = fmaxf(fmaf(cd, bdv.z, fmaf(cc, bcv.z, o.z + bsv.z)), 0.f);
        o.w = fmaxf(fmaf(cd, bdv.w, fmaf(cc, bcv.w, o.w + bsv.w)), 0.f);
        ((float4*)Y)[row * 32 + tx] = o;
    }
}

// ---------------- mean pool per graph + deg re-zero (last launch) ------------
__global__ void __launch_bounds__(DD) k_pool(const float* __restrict__ X,
                                             const int* __restrict__ batch,
                                             float* __restrict__ out) {
    int g = blockIdx.x;
    int c = threadIdx.x;
    int lo = 0, hi = NN;
    while (lo < hi) { int m = (lo + hi) >> 1; if (batch[m] < g) lo = m + 1; else hi = m; }
    int start = lo;
    lo = start; hi = NN;
    while (lo < hi) { int m = (lo + hi) >> 1; if (batch[m] < g + 1) lo = m + 1; else hi = m; }
    int end = lo;

    float s0 = 0.f, s1 = 0.f, s2 = 0.f, s3 = 0.f;
    int n = start;
    for (; n + 3 < end; n += 4) {
        s0 += X[(n + 0) * DD + c];
        s1 += X[(n + 1) * DD + c];
        s2 += X[(n + 2) * DD + c];
        s3 += X[(n + 3) * DD + c];
    }
    for (; n < end; n++) s0 += X[n * DD + c];
    float s = (s0 + s1) + (s2 + s3);
    float cnt = (float)(end - start);
    out[g * DD + c] = s / fmaxf(cnt, 1.0f);

    // restore degree histogram to zero for the next call
    for (int i = g * DD + c; i < NN; i += GG * DD) g_deg[i] = 0;
}

// ---------------- launch ----------------
extern "C" void kernel_launch(void* const* d_in, const int* in_sizes, int n_in,
                              void* d_out, int out_size) {
    const float* X  = (const float*)d_in[0];
    const float* Wd = (const float*)d_in[1];
    const float* bd = (const float*)d_in[2];
    const float* Wc = (const float*)d_in[3];
    const float* bc = (const float*)d_in[4];
    const float* Ws = (const float*)d_in[5];
    const float* bs = (const float*)d_in[6];
    const int* ei   = (const int*)d_in[7];
    const int* et   = (const int*)d_in[8];
    const int* bid  = (const int*)d_in[9];
    const int* srcp = ei;
    const int* dstp = ei + EE;

    void* pA = nullptr;
    void* pB = nullptr;
    cudaGetSymbolAddress(&pA, g_bufA);
    cudaGetSymbolAddress(&pB, g_bufB);
    float* A = (float*)pA;
    float* B = (float*)pB;

    // CSR build (degrees arrive zeroed; k_pool re-zeros them at the end)
    k_count<<<(EE + 255) / 256, 256>>>(dstp);
    k_scan<<<1, 1024>>>();
    k_fill<<<(EE + 255) / 256, 256>>>(srcp, dstp, et);

    const float* cur = X;
    float* outs[3] = { A, B, A };
    for (int l = 0; l < LL; l++) {
        k_aggregate<<<(NN * 32 + 255) / 256, 256>>>(cur); // ncu window (l=0)
        k_gemm<<<(NN + GROWS - 1) / GROWS, 256>>>(cur,
                                        Wd + l * DD * DD, bd + l * DD,
                                        Wc + l * DD * DD, bc + l * DD,
                                        Ws + l * DD * DD, bs + l * DD,
                                        outs[l]);
        cur = outs[l];
    }
    k_pool<<<GG, DD>>>(cur, bid, (float*)d_out);
}

// round 13
// speedup vs baseline: 1.7463x; 1.4265x over previous
#include <cuda_runtime.h>
#include <cuda_bf16.h>
#include <cstdint>

#define NN 50000
#define EE 1600000
#define DD 128
#define GG 64
#define LL 3

// ---------------- scratch (static device globals; no allocation) ----------------
__device__ float g_bufA[NN * DD];
__device__ float g_bufB[NN * DD];
__device__ float g_Sd[NN * DD];
__device__ float g_Sc[NN * DD];
__device__ int   g_deg[NN];          // zero at entry (k_pool re-zeros)
__device__ int   g_cntd[NN];
__device__ int   g_cntc[NN];
__device__ int   g_rowptr[NN + 1];
__device__ int   g_cursor[NN];
__device__ unsigned int g_edge[EE];
// bf16 split of A = [Sd|Sc|X]: row-major [NN][384]
__device__ __nv_bfloat16 g_Ahi[NN * 384];
__device__ __nv_bfloat16 g_Alo[NN * 384];
// bf16 split of W^T: [(l*3+seg)][n=0..127][k=0..127]
__device__ __nv_bfloat16 g_Wthi[9 * 128 * 128];
__device__ __nv_bfloat16 g_Wtlo[9 * 128 * 128];

// ---------------- PTX helpers (baseline sm_80+ features only) ----------------
__device__ __forceinline__ uint32_t smem_to_u32(const void* p) {
    uint32_t a;
    asm("{ .reg .u64 t; cvta.to.shared.u64 t, %1; cvt.u32.u64 %0, t; }"
        : "=r"(a) : "l"(p));
    return a;
}
__device__ __forceinline__ void ldm_x4(uint32_t* r, uint32_t addr) {
    asm volatile("ldmatrix.sync.aligned.m8n8.x4.shared.b16 {%0,%1,%2,%3}, [%4];"
                 : "=r"(r[0]), "=r"(r[1]), "=r"(r[2]), "=r"(r[3]) : "r"(addr));
}
__device__ __forceinline__ void mma_bf16(float* d, const uint32_t* a,
                                         uint32_t b0, uint32_t b1) {
    asm volatile("mma.sync.aligned.m16n8k16.row.col.f32.bf16.bf16.f32 "
                 "{%0,%1,%2,%3}, {%4,%5,%6,%7}, {%8,%9}, {%0,%1,%2,%3};"
                 : "+f"(d[0]), "+f"(d[1]), "+f"(d[2]), "+f"(d[3])
                 : "r"(a[0]), "r"(a[1]), "r"(a[2]), "r"(a[3]), "r"(b0), "r"(b1));
}

// ---------------- CSR build ----------------
__global__ void k_count(const int* __restrict__ dst) {
    int e = blockIdx.x * blockDim.x + threadIdx.x;
    if (e < EE) atomicAdd(&g_deg[dst[e]], 1);
}

__global__ void __launch_bounds__(1024) k_scan() {
    __shared__ int warp_sums[32];
    __shared__ int s_carry;
    int tid = threadIdx.x;
    int lane = tid & 31, wid = tid >> 5;
    if (tid == 0) s_carry = 0;
    __syncthreads();
    for (int base = 0; base < NN; base += 1024) {
        int i = base + tid;
        int v = (i < NN) ? g_deg[i] : 0;
        int x = v;
        #pragma unroll
        for (int off = 1; off < 32; off <<= 1) {
            int y = __shfl_up_sync(0xffffffffu, x, off);
            if (lane >= off) x += y;
        }
        if (lane == 31) warp_sums[wid] = x;
        __syncthreads();
        if (tid < 32) {
            int w = warp_sums[tid];
            #pragma unroll
            for (int off = 1; off < 32; off <<= 1) {
                int y = __shfl_up_sync(0xffffffffu, w, off);
                if (tid >= off) w += y;
            }
            warp_sums[tid] = w;
        }
        __syncthreads();
        int woff = (wid > 0) ? warp_sums[wid - 1] : 0;
        int incl = x + woff;
        if (i < NN) {
            int rp = s_carry + incl - v;
            g_rowptr[i] = rp;
            g_cursor[i] = rp;
        }
        int total = warp_sums[31];
        __syncthreads();
        if (tid == 0) s_carry += total;
        __syncthreads();
    }
    if (tid == 0) g_rowptr[NN] = s_carry;
}

__global__ void k_fill(const int* __restrict__ src, const int* __restrict__ dst,
                       const int* __restrict__ et) {
    int e = blockIdx.x * blockDim.x + threadIdx.x;
    if (e < EE) {
        int d = dst[e];
        int pos = atomicAdd(&g_cursor[d], 1);
        g_edge[pos] = (unsigned int)src[e] | ((unsigned int)et[e] << 31);
    }
}

// ---------------- edge aggregation: warp per dst node (+ type counts) --------
__global__ void __launch_bounds__(256) k_aggregate(const float* __restrict__ X) {
    int w = (blockIdx.x * blockDim.x + threadIdx.x) >> 5;
    int lane = threadIdx.x & 31;
    if (w >= NN) return;
    int beg = g_rowptr[w], end = g_rowptr[w + 1];
    const float4* X4 = (const float4*)X;
    float4 ad = make_float4(0.f, 0.f, 0.f, 0.f);
    float4 ac = make_float4(0.f, 0.f, 0.f, 0.f);
    int nc = 0;
    int j = beg;
    for (; j + 1 < end; j += 2) {
        unsigned int e0 = g_edge[j];
        unsigned int e1 = g_edge[j + 1];
        float4 v0 = __ldg(X4 + (int)(e0 & 0x7fffffffu) * 32 + lane);
        float4 v1 = __ldg(X4 + (int)(e1 & 0x7fffffffu) * 32 + lane);
        nc += (int)(e0 >> 31) + (int)(e1 >> 31);
        if (e0 >> 31) { ac.x += v0.x; ac.y += v0.y; ac.z += v0.z; ac.w += v0.w; }
        else          { ad.x += v0.x; ad.y += v0.y; ad.z += v0.z; ad.w += v0.w; }
        if (e1 >> 31) { ac.x += v1.x; ac.y += v1.y; ac.z += v1.z; ac.w += v1.w; }
        else          { ad.x += v1.x; ad.y += v1.y; ad.z += v1.z; ad.w += v1.w; }
    }
    if (j < end) {
        unsigned int e0 = g_edge[j];
        float4 v0 = __ldg(X4 + (int)(e0 & 0x7fffffffu) * 32 + lane);
        nc += (int)(e0 >> 31);
        if (e0 >> 31) { ac.x += v0.x; ac.y += v0.y; ac.z += v0.z; ac.w += v0.w; }
        else          { ad.x += v0.x; ad.y += v0.y; ad.z += v0.z; ad.w += v0.w; }
    }
    ((float4*)g_Sd)[w * 32 + lane] = ad;
    ((float4*)g_Sc)[w * 32 + lane] = ac;
    if (lane == 0) {
        g_cntc[w] = nc;
        g_cntd[w] = (end - beg) - nc;
    }
}

// ---------------- bf16 hi/lo split of A = [Sd|Sc|X] ----------------
__global__ void __launch_bounds__(256) k_split(const float* __restrict__ Xin) {
    int idx = blockIdx.x * blockDim.x + threadIdx.x;
    if (idx >= NN * 96) return;
    int row = idx / 96, c4 = idx % 96;
    int seg = c4 >> 5, c4i = c4 & 31;
    const float* base = (seg == 0) ? g_Sd : (seg == 1) ? g_Sc : Xin;
    float4 v = __ldg((const float4*)(base + row * DD) + c4i);
    __nv_bfloat16 h0 = __float2bfloat16(v.x), h1 = __float2bfloat16(v.y);
    __nv_bfloat16 h2 = __float2bfloat16(v.z), h3 = __float2bfloat16(v.w);
    __nv_bfloat16 l0 = __float2bfloat16(v.x - __bfloat162float(h0));
    __nv_bfloat16 l1 = __float2bfloat16(v.y - __bfloat162float(h1));
    __nv_bfloat16 l2 = __float2bfloat16(v.z - __bfloat162float(h2));
    __nv_bfloat16 l3 = __float2bfloat16(v.w - __bfloat162float(h3));
    __nv_bfloat162 h01 = __halves2bfloat162(h0, h1), h23 = __halves2bfloat162(h2, h3);
    __nv_bfloat162 l01 = __halves2bfloat162(l0, l1), l23 = __halves2bfloat162(l2, l3);
    uint2 hu, lu;
    hu.x = *reinterpret_cast<unsigned*>(&h01); hu.y = *reinterpret_cast<unsigned*>(&h23);
    lu.x = *reinterpret_cast<unsigned*>(&l01); lu.y = *reinterpret_cast<unsigned*>(&l23);
    *reinterpret_cast<uint2*>(g_Ahi + row * 384 + c4 * 4) = hu;
    *reinterpret_cast<uint2*>(g_Alo + row * 384 + c4 * 4) = lu;
}

// ---------------- W transpose + bf16 split (once per call) ----------------
__global__ void __launch_bounds__(256) k_wprep(const float* __restrict__ Wd,
                                               const float* __restrict__ Wc,
                                               const float* __restrict__ Ws) {
    int idx = blockIdx.x * blockDim.x + threadIdx.x;
    if (idx >= 9 * 128 * 128) return;
    int l3s = idx >> 14;
    int n = (idx >> 7) & 127;
    int k = idx & 127;
    int l = l3s / 3, seg = l3s % 3;
    const float* Wp = (seg == 0) ? Wd : (seg == 1) ? Wc : Ws;
    float v = Wp[l * DD * DD + k * DD + n];
    __nv_bfloat16 h = __float2bfloat16(v);
    __nv_bfloat16 lo = __float2bfloat16(v - __bfloat162float(h));
    g_Wthi[idx] = h;
    g_Wtlo[idx] = lo;
}

// ---------------- mma.sync bf16 GEMM: Y = relu(A@Wt^T + bias), 3-term split --
// Block 128x128, 512 threads, 16 warps (4 m-groups x 4 n-groups, 32x32/warp).
// K=384 in 6 chunks of 64. Tiles in smem, pitch 72 bf16 (144B) -> ldmatrix
// conflict-free. Terms Ahi*Bhi + Ahi*Blo + Alo*Bhi accumulate into one frag.
#define TPB 512
#define PITCH_B 144
#define OFF_BD 0
#define OFF_BC 512
#define OFF_BS 1024
#define OFF_AH 2048
#define OFF_AL (OFF_AH + 128 * PITCH_B)
#define OFF_BHI (OFF_AL + 128 * PITCH_B)
#define OFF_BLO (OFF_BHI + 128 * PITCH_B)
#define MMA_SMEM (OFF_BLO + 128 * PITCH_B)   // 75776 bytes

__global__ void __launch_bounds__(TPB) k_mma(
    const float* __restrict__ bd, const float* __restrict__ bc,
    const float* __restrict__ bs, float* __restrict__ Y, int wt_base)
{
    extern __shared__ __align__(16) char smem[];
    uint32_t sb = smem_to_u32(smem);
    int tid = threadIdx.x;
    int lane = tid & 31, wid = tid >> 5;
    int mg = wid >> 2, ng = wid & 3;
    int rowbase = blockIdx.x * 128;

    if (tid < 128) {
        ((float*)(smem + OFF_BD))[tid] = __ldg(bd + tid);
        ((float*)(smem + OFF_BC))[tid] = __ldg(bc + tid);
        ((float*)(smem + OFF_BS))[tid] = __ldg(bs + tid);
    }

    float acc[2][4][4];
    #pragma unroll
    for (int mt = 0; mt < 2; mt++)
        #pragma unroll
        for (int nt = 0; nt < 4; nt++)
            #pragma unroll
            for (int q = 0; q < 4; q++) acc[mt][nt][q] = 0.f;

    // ldmatrix lane address components (PTX ISA x4 tile ordering)
    int lr = lane & 7;
    int l8 = (lane >> 3) & 1;
    int l16 = lane >> 4;
    uint32_t a_row_add = (uint32_t)(lr + l8 * 8);      // A: tiles m0k0,m8k0,m0k8,m8k8
    uint32_t a_k_add   = (uint32_t)(l16 * 16);         // +8 bf16 = 16B
    uint32_t b_row_add = (uint32_t)(lr + l16 * 8);     // B: tiles n0k0,n0k8,n8k0,n8k8
    uint32_t b_k_add   = (uint32_t)(l8 * 16);

    #pragma unroll 1
    for (int c = 0; c < 6; c++) {
        __syncthreads();                    // bias (c=0) / smem reuse (c>0)
        int seg = c >> 1;
        int kin = (c & 1) * 64;
        // ---- stage A hi/lo (rows of this block, 64 k) ----
        #pragma unroll
        for (int i = 0; i < 2; i++) {
            int e = tid + i * TPB;          // 0..1023
            int r = e >> 3, j = e & 7;
            int grow = rowbase + r;
            uint4 hv = make_uint4(0, 0, 0, 0), lv = make_uint4(0, 0, 0, 0);
            if (grow < NN) {
                hv = __ldg((const uint4*)(g_Ahi + (size_t)grow * 384 + c * 64 + j * 8));
                lv = __ldg((const uint4*)(g_Alo + (size_t)grow * 384 + c * 64 + j * 8));
            }
            *(uint4*)(smem + OFF_AH + r * PITCH_B + j * 16) = hv;
            *(uint4*)(smem + OFF_AL + r * PITCH_B + j * 16) = lv;
        }
        // ---- stage B hi/lo (all 128 n, 64 k of this seg) ----
        #pragma unroll
        for (int i = 0; i < 2; i++) {
            int e = tid + i * TPB;
            int n = e >> 3, j = e & 7;
            const __nv_bfloat16* ph = g_Wthi + wt_base + seg * 16384 + n * 128 + kin + j * 8;
            const __nv_bfloat16* pl = g_Wtlo + wt_base + seg * 16384 + n * 128 + kin + j * 8;
            uint4 hv = __ldg((const uint4*)ph);
            uint4 lv = __ldg((const uint4*)pl);
            *(uint4*)(smem + OFF_BHI + n * PITCH_B + j * 16) = hv;
            *(uint4*)(smem + OFF_BLO + n * PITCH_B + j * 16) = lv;
        }
        __syncthreads();
        // ---- compute: 4 k16-steps ----
        #pragma unroll
        for (int ks = 0; ks < 4; ks++) {
            uint32_t kb = (uint32_t)(ks * 32);     // 16 bf16 = 32B
            uint32_t ah0[4], ah1[4], al0[4], al1[4];
            uint32_t bh01[4], bh23[4], bl01[4], bl23[4];
            uint32_t ar0 = (uint32_t)(mg * 32) + a_row_add;
            ldm_x4(ah0, sb + OFF_AH + ar0 * PITCH_B + kb + a_k_add);
            ldm_x4(ah1, sb + OFF_AH + (ar0 + 16) * PITCH_B + kb + a_k_add);
            ldm_x4(al0, sb + OFF_AL + ar0 * PITCH_B + kb + a_k_add);
            ldm_x4(al1, sb + OFF_AL + (ar0 + 16) * PITCH_B + kb + a_k_add);
            uint32_t br0 = (uint32_t)(ng * 32) + b_row_add;
            ldm_x4(bh01, sb + OFF_BHI + br0 * PITCH_B + kb + b_k_add);
            ldm_x4(bh23, sb + OFF_BHI + (br0 + 16) * PITCH_B + kb + b_k_add);
            ldm_x4(bl01, sb + OFF_BLO + br0 * PITCH_B + kb + b_k_add);
            ldm_x4(bl23, sb + OFF_BLO + (br0 + 16) * PITCH_B + kb + b_k_add);

            const uint32_t* Ah[2] = { ah0, ah1 };
            const uint32_t* Al[2] = { al0, al1 };
            uint32_t bh[4][2] = { {bh01[0], bh01[1]}, {bh01[2], bh01[3]},
                                  {bh23[0], bh23[1]}, {bh23[2], bh23[3]} };
            uint32_t bl[4][2] = { {bl01[0], bl01[1]}, {bl01[2], bl01[3]},
                                  {bl23[0], bl23[1]}, {bl23[2], bl23[3]} };
            #pragma unroll
            for (int mt = 0; mt < 2; mt++)
                #pragma unroll
                for (int nt = 0; nt < 4; nt++) {
                    mma_bf16(acc[mt][nt], Ah[mt], bh[nt][0], bh[nt][1]); // hi*hi
                    mma_bf16(acc[mt][nt], Ah[mt], bl[nt][0], bl[nt][1]); // hi*lo
                    mma_bf16(acc[mt][nt], Al[mt], bh[nt][0], bh[nt][1]); // lo*hi
                }
        }
    }

    // ---- epilogue: bias + relu + store ----
    int gq = lane >> 2, tig = lane & 3;
    const float* s_bd = (const float*)(smem + OFF_BD);
    const float* s_bc = (const float*)(smem + OFF_BC);
    const float* s_bs = (const float*)(smem + OFF_BS);
    #pragma unroll
    for (int mt = 0; mt < 2; mt++) {
        int r0 = rowbase + mg * 32 + mt * 16 + gq;
        int r1 = r0 + 8;
        float cd0 = 0.f, cc0 = 0.f, cd1 = 0.f, cc1 = 0.f;
        if (r0 < NN) { cd0 = (float)g_cntd[r0]; cc0 = (float)g_cntc[r0]; }
        if (r1 < NN) { cd1 = (float)g_cntd[r1]; cc1 = (float)g_cntc[r1]; }
        #pragma unroll
        for (int nt = 0; nt < 4; nt++) {
            int col = ng * 32 + nt * 8 + tig * 2;
            float bdx = s_bd[col], bdy = s_bd[col + 1];
            float bcx = s_bc[col], bcy = s_bc[col + 1];
            float bsx = s_bs[col], bsy = s_bs[col + 1];
            if (r0 < NN) {
                float2 o;
                o.x = fmaxf(fmaf(cd0, bdx, fmaf(cc0, bcx, acc[mt][nt][0] + bsx)), 0.f);
                o.y = fmaxf(fmaf(cd0, bdy, fmaf(cc0, bcy, acc[mt][nt][1] + bsy)), 0.f);
                *(float2*)(Y + (size_t)r0 * DD + col) = o;
            }
            if (r1 < NN) {
                float2 o;
                o.x = fmaxf(fmaf(cd1, bdx, fmaf(cc1, bcx, acc[mt][nt][2] + bsx)), 0.f);
                o.y = fmaxf(fmaf(cd1, bdy, fmaf(cc1, bcy, acc[mt][nt][3] + bsy)), 0.f);
                *(float2*)(Y + (size_t)r1 * DD + col) = o;
            }
        }
    }
}

// ---------------- mean pool per graph + deg re-zero (last launch) ------------
__global__ void __launch_bounds__(DD) k_pool(const float* __restrict__ X,
                                             const int* __restrict__ batch,
                                             float* __restrict__ out) {
    int g = blockIdx.x;
    int c = threadIdx.x;
    int lo = 0, hi = NN;
    while (lo < hi) { int m = (lo + hi) >> 1; if (batch[m] < g) lo = m + 1; else hi = m; }
    int start = lo;
    lo = start; hi = NN;
    while (lo < hi) { int m = (lo + hi) >> 1; if (batch[m] < g + 1) lo = m + 1; else hi = m; }
    int end = lo;

    float s0 = 0.f, s1 = 0.f, s2 = 0.f, s3 = 0.f;
    int n = start;
    for (; n + 3 < end; n += 4) {
        s0 += X[(n + 0) * DD + c];
        s1 += X[(n + 1) * DD + c];
        s2 += X[(n + 2) * DD + c];
        s3 += X[(n + 3) * DD + c];
    }
    for (; n < end; n++) s0 += X[n * DD + c];
    float s = (s0 + s1) + (s2 + s3);
    float cnt = (float)(end - start);
    out[g * DD + c] = s / fmaxf(cnt, 1.0f);

    for (int i = g * DD + c; i < NN; i += GG * DD) g_deg[i] = 0;
}

// ---------------- launch ----------------
extern "C" void kernel_launch(void* const* d_in, const int* in_sizes, int n_in,
                              void* d_out, int out_size) {
    const float* X  = (const float*)d_in[0];
    const float* Wd = (const float*)d_in[1];
    const float* bd = (const float*)d_in[2];
    const float* Wc = (const float*)d_in[3];
    const float* bc = (const float*)d_in[4];
    const float* Ws = (const float*)d_in[5];
    const float* bs = (const float*)d_in[6];
    const int* ei   = (const int*)d_in[7];
    const int* et   = (const int*)d_in[8];
    const int* bid  = (const int*)d_in[9];
    const int* srcp = ei;
    const int* dstp = ei + EE;

    void* pA = nullptr;
    void* pB = nullptr;
    cudaGetSymbolAddress(&pA, g_bufA);
    cudaGetSymbolAddress(&pB, g_bufB);
    float* A = (float*)pA;
    float* B = (float*)pB;

    cudaFuncSetAttribute(k_mma, cudaFuncAttributeMaxDynamicSharedMemorySize, MMA_SMEM);

    // CSR build + weight prep
    k_count<<<(EE + 255) / 256, 256>>>(dstp);
    k_scan<<<1, 1024>>>();
    k_fill<<<(EE + 255) / 256, 256>>>(srcp, dstp, et);
    k_wprep<<<(9 * 128 * 128 + 255) / 256, 256>>>(Wd, Wc, Ws);

    const float* cur = X;
    float* outs[3] = { A, B, A };
    for (int l = 0; l < LL; l++) {
        k_aggregate<<<(NN * 32 + 255) / 256, 256>>>(cur);
        k_split<<<(NN * 96 + 255) / 256, 256>>>(cur);
        k_mma<<<(NN + 127) / 128, TPB, MMA_SMEM>>>(bd + l * DD, bc + l * DD,
                                                   bs + l * DD, outs[l],
                                                   l * 3 * 16384);
        cur = outs[l];
    }
    k_pool<<<GG, DD>>>(cur, bid, (float*)d_out);
}

// round 15
// speedup vs baseline: 1.9638x; 1.1245x over previous
#include <cuda_runtime.h>
#include <cuda_bf16.h>
#include <cstdint>

#define NN 50000
#define EE 1600000
#define DD 128
#define GG 64
#define LL 3

// ---------------- scratch (static device globals; no allocation) ----------------
__device__ float g_bufA[NN * DD];
__device__ float g_bufB[NN * DD];
__device__ int   g_deg[NN];          // zero at entry (k_pool re-zeros)
__device__ int   g_cntd[NN];
__device__ int   g_cntc[NN];
__device__ int   g_rowptr[NN + 1];
__device__ int   g_cursor[NN];
__device__ unsigned int g_edge[EE];
// bf16 split of A = [Sd|Sc|X]: row-major [NN][384]
// segs 0/1 written by k_aggregate, seg 2 by k_split_x (l=0) / k_mma epilogue
__device__ __nv_bfloat16 g_Ahi[NN * 384];
__device__ __nv_bfloat16 g_Alo[NN * 384];
// bf16 split of W^T: [(l*3+seg)][n=0..127][k=0..127]
__device__ __nv_bfloat16 g_Wthi[9 * 128 * 128];
__device__ __nv_bfloat16 g_Wtlo[9 * 128 * 128];

// ---------------- PTX / split helpers ----------------
__device__ __forceinline__ uint32_t smem_to_u32(const void* p) {
    uint32_t a;
    asm("{ .reg .u64 t; cvta.to.shared.u64 t, %1; cvt.u32.u64 %0, t; }"
        : "=r"(a) : "l"(p));
    return a;
}
__device__ __forceinline__ void ldm_x4(uint32_t* r, uint32_t addr) {
    asm volatile("ldmatrix.sync.aligned.m8n8.x4.shared.b16 {%0,%1,%2,%3}, [%4];"
                 : "=r"(r[0]), "=r"(r[1]), "=r"(r[2]), "=r"(r[3]) : "r"(addr));
}
__device__ __forceinline__ void mma_bf16(float* d, const uint32_t* a,
                                         uint32_t b0, uint32_t b1) {
    asm volatile("mma.sync.aligned.m16n8k16.row.col.f32.bf16.bf16.f32 "
                 "{%0,%1,%2,%3}, {%4,%5,%6,%7}, {%8,%9}, {%0,%1,%2,%3};"
                 : "+f"(d[0]), "+f"(d[1]), "+f"(d[2]), "+f"(d[3])
                 : "r"(a[0]), "r"(a[1]), "r"(a[2]), "r"(a[3]), "r"(b0), "r"(b1));
}
// split float4 -> packed bf16 hi (uint2) + lo (uint2)
__device__ __forceinline__ void split4(float4 v, uint2& hu, uint2& lu) {
    __nv_bfloat16 h0 = __float2bfloat16(v.x), h1 = __float2bfloat16(v.y);
    __nv_bfloat16 h2 = __float2bfloat16(v.z), h3 = __float2bfloat16(v.w);
    __nv_bfloat16 l0 = __float2bfloat16(v.x - __bfloat162float(h0));
    __nv_bfloat16 l1 = __float2bfloat16(v.y - __bfloat162float(h1));
    __nv_bfloat16 l2 = __float2bfloat16(v.z - __bfloat162float(h2));
    __nv_bfloat16 l3 = __float2bfloat16(v.w - __bfloat162float(h3));
    __nv_bfloat162 h01 = __halves2bfloat162(h0, h1), h23 = __halves2bfloat162(h2, h3);
    __nv_bfloat162 l01 = __halves2bfloat162(l0, l1), l23 = __halves2bfloat162(l2, l3);
    hu.x = *reinterpret_cast<unsigned*>(&h01); hu.y = *reinterpret_cast<unsigned*>(&h23);
    lu.x = *reinterpret_cast<unsigned*>(&l01); lu.y = *reinterpret_cast<unsigned*>(&l23);
}
// split float2 -> packed bf16x2 hi + lo (uint32)
__device__ __forceinline__ void split2(float x, float y, uint32_t& hp, uint32_t& lp) {
    __nv_bfloat16 h0 = __float2bfloat16(x), h1 = __float2bfloat16(y);
    __nv_bfloat16 l0 = __float2bfloat16(x - __bfloat162float(h0));
    __nv_bfloat16 l1 = __float2bfloat16(y - __bfloat162float(h1));
    __nv_bfloat162 h01 = __halves2bfloat162(h0, h1);
    __nv_bfloat162 l01 = __halves2bfloat162(l0, l1);
    hp = *reinterpret_cast<unsigned*>(&h01);
    lp = *reinterpret_cast<unsigned*>(&l01);
}

// ---------------- CSR build ----------------
__global__ void k_count(const int* __restrict__ dst) {
    int e = blockIdx.x * blockDim.x + threadIdx.x;
    if (e < EE) atomicAdd(&g_deg[dst[e]], 1);
}

__global__ void __launch_bounds__(1024) k_scan() {
    __shared__ int warp_sums[32];
    __shared__ int s_carry;
    int tid = threadIdx.x;
    int lane = tid & 31, wid = tid >> 5;
    if (tid == 0) s_carry = 0;
    __syncthreads();
    for (int base = 0; base < NN; base += 1024) {
        int i = base + tid;
        int v = (i < NN) ? g_deg[i] : 0;
        int x = v;
        #pragma unroll
        for (int off = 1; off < 32; off <<= 1) {
            int y = __shfl_up_sync(0xffffffffu, x, off);
            if (lane >= off) x += y;
        }
        if (lane == 31) warp_sums[wid] = x;
        __syncthreads();
        if (tid < 32) {
            int w = warp_sums[tid];
            #pragma unroll
            for (int off = 1; off < 32; off <<= 1) {
                int y = __shfl_up_sync(0xffffffffu, w, off);
                if (tid >= off) w += y;
            }
            warp_sums[tid] = w;
        }
        __syncthreads();
        int woff = (wid > 0) ? warp_sums[wid - 1] : 0;
        int incl = x + woff;
        if (i < NN) {
            int rp = s_carry + incl - v;
            g_rowptr[i] = rp;
            g_cursor[i] = rp;
        }
        int total = warp_sums[31];
        __syncthreads();
        if (tid == 0) s_carry += total;
        __syncthreads();
    }
    if (tid == 0) g_rowptr[NN] = s_carry;
}

__global__ void k_fill(const int* __restrict__ src, const int* __restrict__ dst,
                       const int* __restrict__ et) {
    int e = blockIdx.x * blockDim.x + threadIdx.x;
    if (e < EE) {
        int d = dst[e];
        int pos = atomicAdd(&g_cursor[d], 1);
        g_edge[pos] = (unsigned int)src[e] | ((unsigned int)et[e] << 31);
    }
}

// ---------------- edge aggregation: warp per dst node, bf16-split output ----
__global__ void __launch_bounds__(256) k_aggregate(const float* __restrict__ X) {
    int w = (blockIdx.x * blockDim.x + threadIdx.x) >> 5;
    int lane = threadIdx.x & 31;
    if (w >= NN) return;
    int beg = g_rowptr[w], end = g_rowptr[w + 1];
    const float4* X4 = (const float4*)X;
    float4 ad = make_float4(0.f, 0.f, 0.f, 0.f);
    float4 ac = make_float4(0.f, 0.f, 0.f, 0.f);
    int nc = 0;
    int j = beg;
    for (; j + 1 < end; j += 2) {
        unsigned int e0 = g_edge[j];
        unsigned int e1 = g_edge[j + 1];
        float4 v0 = __ldg(X4 + (int)(e0 & 0x7fffffffu) * 32 + lane);
        float4 v1 = __ldg(X4 + (int)(e1 & 0x7fffffffu) * 32 + lane);
        nc += (int)(e0 >> 31) + (int)(e1 >> 31);
        if (e0 >> 31) { ac.x += v0.x; ac.y += v0.y; ac.z += v0.z; ac.w += v0.w; }
        else          { ad.x += v0.x; ad.y += v0.y; ad.z += v0.z; ad.w += v0.w; }
        if (e1 >> 31) { ac.x += v1.x; ac.y += v1.y; ac.z += v1.z; ac.w += v1.w; }
        else          { ad.x += v1.x; ad.y += v1.y; ad.z += v1.z; ad.w += v1.w; }
    }
    if (j < end) {
        unsigned int e0 = g_edge[j];
        float4 v0 = __ldg(X4 + (int)(e0 & 0x7fffffffu) * 32 + lane);
        nc += (int)(e0 >> 31);
        if (e0 >> 31) { ac.x += v0.x; ac.y += v0.y; ac.z += v0.z; ac.w += v0.w; }
        else          { ad.x += v0.x; ad.y += v0.y; ad.z += v0.z; ad.w += v0.w; }
    }
    // write bf16 hi/lo split directly (segs 0 = data, 1 = ctrl)
    uint2 hu, lu;
    split4(ad, hu, lu);
    *reinterpret_cast<uint2*>(g_Ahi + (size_t)w * 384 + lane * 4) = hu;
    *reinterpret_cast<uint2*>(g_Alo + (size_t)w * 384 + lane * 4) = lu;
    split4(ac, hu, lu);
    *reinterpret_cast<uint2*>(g_Ahi + (size_t)w * 384 + 128 + lane * 4) = hu;
    *reinterpret_cast<uint2*>(g_Alo + (size_t)w * 384 + 128 + lane * 4) = lu;
    if (lane == 0) {
        g_cntc[w] = nc;
        g_cntd[w] = (end - beg) - nc;
    }
}

// ---------------- seg-2 split of the input X (layer 0 only) ----------------
__global__ void __launch_bounds__(256) k_split_x(const float* __restrict__ Xin) {
    int idx = blockIdx.x * blockDim.x + threadIdx.x;
    if (idx >= NN * 32) return;
    int row = idx >> 5, c4 = idx & 31;
    float4 v = __ldg((const float4*)(Xin + (size_t)row * DD) + c4);
    uint2 hu, lu;
    split4(v, hu, lu);
    *reinterpret_cast<uint2*>(g_Ahi + (size_t)row * 384 + 256 + c4 * 4) = hu;
    *reinterpret_cast<uint2*>(g_Alo + (size_t)row * 384 + 256 + c4 * 4) = lu;
}

// ---------------- W transpose + bf16 split (once per call) ----------------
__global__ void __launch_bounds__(256) k_wprep(const float* __restrict__ Wd,
                                               const float* __restrict__ Wc,
                                               const float* __restrict__ Ws) {
    int idx = blockIdx.x * blockDim.x + threadIdx.x;
    if (idx >= 9 * 128 * 128) return;
    int l3s = idx >> 14;
    int n = (idx >> 7) & 127;
    int k = idx & 127;
    int l = l3s / 3, seg = l3s % 3;
    const float* Wp = (seg == 0) ? Wd : (seg == 1) ? Wc : Ws;
    float v = Wp[l * DD * DD + k * DD + n];
    __nv_bfloat16 h = __float2bfloat16(v);
    __nv_bfloat16 lo = __float2bfloat16(v - __bfloat162float(h));
    g_Wthi[idx] = h;
    g_Wtlo[idx] = lo;
}

// ---------------- mma.sync bf16 GEMM: Y = relu(A@Wt^T + bias), 3-term split --
// Block 128x128, 512 threads, 16 warps (4 m-groups x 4 n-groups, 32x32/warp).
// K=384 in 6 chunks of 64. Epilogue also emits seg-2 bf16 split for the next
// layer (do_split). Pitch 72 bf16 (144B) keeps ldmatrix conflict-free.
#define TPB 512
#define PITCH_B 144
#define OFF_BD 0
#define OFF_BC 512
#define OFF_BS 1024
#define OFF_AH 2048
#define OFF_AL (OFF_AH + 128 * PITCH_B)
#define OFF_BHI (OFF_AL + 128 * PITCH_B)
#define OFF_BLO (OFF_BHI + 128 * PITCH_B)
#define MMA_SMEM (OFF_BLO + 128 * PITCH_B)   // 75776 bytes

__global__ void __launch_bounds__(TPB) k_mma(
    const float* __restrict__ bd, const float* __restrict__ bc,
    const float* __restrict__ bs, float* __restrict__ Y, int wt_base,
    int do_split)
{
    extern __shared__ __align__(16) char smem[];
    uint32_t sb = smem_to_u32(smem);
    int tid = threadIdx.x;
    int lane = tid & 31, wid = tid >> 5;
    int mg = wid >> 2, ng = wid & 3;
    int rowbase = blockIdx.x * 128;

    if (tid < 128) {
        ((float*)(smem + OFF_BD))[tid] = __ldg(bd + tid);
        ((float*)(smem + OFF_BC))[tid] = __ldg(bc + tid);
        ((float*)(smem + OFF_BS))[tid] = __ldg(bs + tid);
    }

    float acc[2][4][4];
    #pragma unroll
    for (int mt = 0; mt < 2; mt++)
        #pragma unroll
        for (int nt = 0; nt < 4; nt++)
            #pragma unroll
            for (int q = 0; q < 4; q++) acc[mt][nt][q] = 0.f;

    int lr = lane & 7;
    int l8 = (lane >> 3) & 1;
    int l16 = lane >> 4;
    uint32_t a_row_add = (uint32_t)(lr + l8 * 8);
    uint32_t a_k_add   = (uint32_t)(l16 * 16);
    uint32_t b_row_add = (uint32_t)(lr + l16 * 8);
    uint32_t b_k_add   = (uint32_t)(l8 * 16);

    #pragma unroll 1
    for (int c = 0; c < 6; c++) {
        __syncthreads();
        int seg = c >> 1;
        int kin = (c & 1) * 64;
        #pragma unroll
        for (int i = 0; i < 2; i++) {
            int e = tid + i * TPB;
            int r = e >> 3, j = e & 7;
            int grow = rowbase + r;
            uint4 hv = make_uint4(0, 0, 0, 0), lv = make_uint4(0, 0, 0, 0);
            if (grow < NN) {
                hv = __ldg((const uint4*)(g_Ahi + (size_t)grow * 384 + c * 64 + j * 8));
                lv = __ldg((const uint4*)(g_Alo + (size_t)grow * 384 + c * 64 + j * 8));
            }
            *(uint4*)(smem + OFF_AH + r * PITCH_B + j * 16) = hv;
            *(uint4*)(smem + OFF_AL + r * PITCH_B + j * 16) = lv;
        }
        #pragma unroll
        for (int i = 0; i < 2; i++) {
            int e = tid + i * TPB;
            int n = e >> 3, j = e & 7;
            const __nv_bfloat16* ph = g_Wthi + wt_base + seg * 16384 + n * 128 + kin + j * 8;
            const __nv_bfloat16* pl = g_Wtlo + wt_base + seg * 16384 + n * 128 + kin + j * 8;
            uint4 hv = __ldg((const uint4*)ph);
            uint4 lv = __ldg((const uint4*)pl);
            *(uint4*)(smem + OFF_BHI + n * PITCH_B + j * 16) = hv;
            *(uint4*)(smem + OFF_BLO + n * PITCH_B + j * 16) = lv;
        }
        __syncthreads();
        #pragma unroll
        for (int ks = 0; ks < 4; ks++) {
            uint32_t kb = (uint32_t)(ks * 32);
            uint32_t ah0[4], ah1[4], al0[4], al1[4];
            uint32_t bh01[4], bh23[4], bl01[4], bl23[4];
            uint32_t ar0 = (uint32_t)(mg * 32) + a_row_add;
            ldm_x4(ah0, sb + OFF_AH + ar0 * PITCH_B + kb + a_k_add);
            ldm_x4(ah1, sb + OFF_AH + (ar0 + 16) * PITCH_B + kb + a_k_add);
            ldm_x4(al0, sb + OFF_AL + ar0 * PITCH_B + kb + a_k_add);
            ldm_x4(al1, sb + OFF_AL + (ar0 + 16) * PITCH_B + kb + a_k_add);
            uint32_t br0 = (uint32_t)(ng * 32) + b_row_add;
            ldm_x4(bh01, sb + OFF_BHI + br0 * PITCH_B + kb + b_k_add);
            ldm_x4(bh23, sb + OFF_BHI + (br0 + 16) * PITCH_B + kb + b_k_add);
            ldm_x4(bl01, sb + OFF_BLO + br0 * PITCH_B + kb + b_k_add);
            ldm_x4(bl23, sb + OFF_BLO + (br0 + 16) * PITCH_B + kb + b_k_add);

            const uint32_t* Ah[2] = { ah0, ah1 };
            const uint32_t* Al[2] = { al0, al1 };
            uint32_t bh[4][2] = { {bh01[0], bh01[1]}, {bh01[2], bh01[3]},
                                  {bh23[0], bh23[1]}, {bh23[2], bh23[3]} };
            uint32_t bl[4][2] = { {bl01[0], bl01[1]}, {bl01[2], bl01[3]},
                                  {bl23[0], bl23[1]}, {bl23[2], bl23[3]} };
            #pragma unroll
            for (int mt = 0; mt < 2; mt++)
                #pragma unroll
                for (int nt = 0; nt < 4; nt++) {
                    mma_bf16(acc[mt][nt], Ah[mt], bh[nt][0], bh[nt][1]);
                    mma_bf16(acc[mt][nt], Ah[mt], bl[nt][0], bl[nt][1]);
                    mma_bf16(acc[mt][nt], Al[mt], bh[nt][0], bh[nt][1]);
                }
        }
    }

    // ---- epilogue: bias + relu + store (fp32 Y + optional seg-2 split) ----
    int gq = lane >> 2, tig = lane & 3;
    const float* s_bd = (const float*)(smem + OFF_BD);
    const float* s_bc = (const float*)(smem + OFF_BC);
    const float* s_bs = (const float*)(smem + OFF_BS);
    #pragma unroll
    for (int mt = 0; mt < 2; mt++) {
        int r0 = rowbase + mg * 32 + mt * 16 + gq;
        int r1 = r0 + 8;
        float cd0 = 0.f, cc0 = 0.f, cd1 = 0.f, cc1 = 0.f;
        if (r0 < NN) { cd0 = (float)g_cntd[r0]; cc0 = (float)g_cntc[r0]; }
        if (r1 < NN) { cd1 = (float)g_cntd[r1]; cc1 = (float)g_cntc[r1]; }
        #pragma unroll
        for (int nt = 0; nt < 4; nt++) {
            int col = ng * 32 + nt * 8 + tig * 2;
            float bdx = s_bd[col], bdy = s_bd[col + 1];
            float bcx = s_bc[col], bcy = s_bc[col + 1];
            float bsx = s_bs[col], bsy = s_bs[col + 1];
            if (r0 < NN) {
                float2 o;
                o.x = fmaxf(fmaf(cd0, bdx, fmaf(cc0, bcx, acc[mt][nt][0] + bsx)), 0.f);
                o.y = fmaxf(fmaf(cd0, bdy, fmaf(cc0, bcy, acc[mt][nt][1] + bsy)), 0.f);
                *(float2*)(Y + (size_t)r0 * DD + col) = o;
                if (do_split) {
                    uint32_t hp, lp;
                    split2(o.x, o.y, hp, lp);
                    *reinterpret_cast<uint32_t*>(g_Ahi + (size_t)r0 * 384 + 256 + col) = hp;
                    *reinterpret_cast<uint32_t*>(g_Alo + (size_t)r0 * 384 + 256 + col) = lp;
                }
            }
            if (r1 < NN) {
                float2 o;
                o.x = fmaxf(fmaf(cd1, bdx, fmaf(cc1, bcx, acc[mt][nt][2] + bsx)), 0.f);
                o.y = fmaxf(fmaf(cd1, bdy, fmaf(cc1, bcy, acc[mt][nt][3] + bsy)), 0.f);
                *(float2*)(Y + (size_t)r1 * DD + col) = o;
                if (do_split) {
                    uint32_t hp, lp;
                    split2(o.x, o.y, hp, lp);
                    *reinterpret_cast<uint32_t*>(g_Ahi + (size_t)r1 * 384 + 256 + col) = hp;
                    *reinterpret_cast<uint32_t*>(g_Alo + (size_t)r1 * 384 + 256 + col) = lp;
                }
            }
        }
    }
}

// ---------------- mean pool per graph + deg re-zero (last launch) ------------
__global__ void __launch_bounds__(DD) k_pool(const float* __restrict__ X,
                                             const int* __restrict__ batch,
                                             float* __restrict__ out) {
    int g = blockIdx.x;
    int c = threadIdx.x;
    int lo = 0, hi = NN;
    while (lo < hi) { int m = (lo + hi) >> 1; if (batch[m] < g) lo = m + 1; else hi = m; }
    int start = lo;
    lo = start; hi = NN;
    while (lo < hi) { int m = (lo + hi) >> 1; if (batch[m] < g + 1) lo = m + 1; else hi = m; }
    int end = lo;

    float s0 = 0.f, s1 = 0.f, s2 = 0.f, s3 = 0.f;
    int n = start;
    for (; n + 3 < end; n += 4) {
        s0 += X[(n + 0) * DD + c];
        s1 += X[(n + 1) * DD + c];
        s2 += X[(n + 2) * DD + c];
        s3 += X[(n + 3) * DD + c];
    }
    for (; n < end; n++) s0 += X[n * DD + c];
    float s = (s0 + s1) + (s2 + s3);
    float cnt = (float)(end - start);
    out[g * DD + c] = s / fmaxf(cnt, 1.0f);

    for (int i = g * DD + c; i < NN; i += GG * DD) g_deg[i] = 0;
}

// ---------------- launch ----------------
extern "C" void kernel_launch(void* const* d_in, const int* in_sizes, int n_in,
                              void* d_out, int out_size) {
    const float* X  = (const float*)d_in[0];
    const float* Wd = (const float*)d_in[1];
    const float* bd = (const float*)d_in[2];
    const float* Wc = (const float*)d_in[3];
    const float* bc = (const float*)d_in[4];
    const float* Ws = (const float*)d_in[5];
    const float* bs = (const float*)d_in[6];
    const int* ei   = (const int*)d_in[7];
    const int* et   = (const int*)d_in[8];
    const int* bid  = (const int*)d_in[9];
    const int* srcp = ei;
    const int* dstp = ei + EE;

    void* pA = nullptr;
    void* pB = nullptr;
    cudaGetSymbolAddress(&pA, g_bufA);
    cudaGetSymbolAddress(&pB, g_bufB);
    float* A = (float*)pA;
    float* B = (float*)pB;

    cudaFuncSetAttribute(k_mma, cudaFuncAttributeMaxDynamicSharedMemorySize, MMA_SMEM);

    // CSR build + weight prep + layer-0 X split
    k_count<<<(EE + 255) / 256, 256>>>(dstp);
    k_scan<<<1, 1024>>>();
    k_fill<<<(EE + 255) / 256, 256>>>(srcp, dstp, et);
    k_wprep<<<(9 * 128 * 128 + 255) / 256, 256>>>(Wd, Wc, Ws);
    k_split_x<<<(NN * 32 + 255) / 256, 256>>>(X);

    const float* cur = X;
    float* outs[3] = { A, B, A };
    for (int l = 0; l < LL; l++) {
        k_aggregate<<<(NN * 32 + 255) / 256, 256>>>(cur);
        k_mma<<<(NN + 127) / 128, TPB, MMA_SMEM>>>(bd + l * DD, bc + l * DD,
                                                   bs + l * DD, outs[l],
                                                   l * 3 * 16384,
                                                   (l < LL - 1) ? 1 : 0);
        cur = outs[l];
    }
    k_pool<<<GG, DD>>>(cur, bid, (float*)d_out);
}